// round 1
// baseline (speedup 1.0000x reference)
#include <cuda_runtime.h>
#include <cuda_bf16.h>
#include <math.h>

#define BS 2
#define SEQ 2048
#define DIM 768
#define NH 12
#define HD 64
#define WINDOW 64
#define ROPE_BASE 10000.0f

#define QT 64          // query tile
#define KT 192         // key window per tile: [i0-64, i0+127]
#define LDK 65         // padded K/V smem row stride (floats)

// ---------------- scratch (static device memory; no allocs) ----------------
__device__ float g_qkv[BS * SEQ * 3 * DIM];          // [b, s, 3, nh, hd]
__device__ float g_q[BS * NH * SEQ * HD];            // [b, h, s, d]
__device__ float g_k[BS * NH * SEQ * HD];
__device__ float g_v[BS * NH * SEQ * HD];
__device__ float g_att[BS * SEQ * DIM];              // [b, s, h*HD + d]

// ---------------- classic 128x128x8 fp32 SGEMM, 256 threads, 8x8 micro ----
__global__ __launch_bounds__(256) void sgemm128(
    const float* __restrict__ A, const float* __restrict__ B,
    float* __restrict__ C, int M, int N, int K)
{
    __shared__ float As[8][128];
    __shared__ float Bs[8][128];

    const int tid = threadIdx.x;
    const int bm = blockIdx.y * 128;
    const int bn = blockIdx.x * 128;

    const int a_row = tid >> 1;             // 0..127
    const int a_col = (tid & 1) * 4;        // 0 or 4
    const int b_row = tid >> 5;             // 0..7
    const int b_col = (tid & 31) * 4;       // 0..124

    const int tx = tid & 15;                // 0..15
    const int ty = tid >> 4;                // 0..15

    float acc[8][8];
#pragma unroll
    for (int i = 0; i < 8; i++)
#pragma unroll
        for (int j = 0; j < 8; j++) acc[i][j] = 0.0f;

    for (int k0 = 0; k0 < K; k0 += 8) {
        float4 av = *(const float4*)(A + (long)(bm + a_row) * K + k0 + a_col);
        As[a_col + 0][a_row] = av.x;
        As[a_col + 1][a_row] = av.y;
        As[a_col + 2][a_row] = av.z;
        As[a_col + 3][a_row] = av.w;
        float4 bv = *(const float4*)(B + (long)(k0 + b_row) * N + bn + b_col);
        *(float4*)(&Bs[b_row][b_col]) = bv;
        __syncthreads();

#pragma unroll
        for (int k = 0; k < 8; k++) {
            float a_frag[8], b_frag[8];
#pragma unroll
            for (int i = 0; i < 8; i++) a_frag[i] = As[k][ty * 8 + i];
#pragma unroll
            for (int j = 0; j < 8; j++) b_frag[j] = Bs[k][tx * 8 + j];
#pragma unroll
            for (int i = 0; i < 8; i++)
#pragma unroll
                for (int j = 0; j < 8; j++)
                    acc[i][j] = fmaf(a_frag[i], b_frag[j], acc[i][j]);
        }
        __syncthreads();
    }

#pragma unroll
    for (int i = 0; i < 8; i++) {
        float* crow = C + (long)(bm + ty * 8 + i) * N + bn + tx * 8;
#pragma unroll
        for (int j = 0; j < 8; j += 4) {
            float4 v = make_float4(acc[i][j], acc[i][j + 1], acc[i][j + 2], acc[i][j + 3]);
            *(float4*)(crow + j) = v;
        }
    }
}

// ---------------- RoPE + split/transpose: qkv[b,s,3,h,d] -> q/k/v[b,h,s,d] --
__global__ void rope_split(const float* __restrict__ qkv,
                           float* __restrict__ q, float* __restrict__ k,
                           float* __restrict__ v)
{
    int idx = blockIdx.x * blockDim.x + threadIdx.x;
    const int total = BS * SEQ * NH * HD;
    if (idx >= total) return;
    int d = idx % HD;
    int h = (idx / HD) % NH;
    int s = (idx / (HD * NH)) % SEQ;
    int b = idx / (HD * NH * SEQ);

    const float* base = qkv + (((long)(b * SEQ + s) * 3) * NH + h) * HD;
    float qv = base[d];
    float kv = base[NH * HD + d];
    float vv = base[2 * NH * HD + d];

    int fi = d & 31;
    // inv_freq = ROPE_BASE ^ (-2*fi/HD)
    float inv_freq = expf(-(2.0f * (float)fi / (float)HD) * logf(ROPE_BASE));
    float angle = (float)s * inv_freq;
    float c = cosf(angle), sn = sinf(angle);

    float qo, ko;
    if (d < 32) {
        qo = qv * c - base[d + 32] * sn;
        ko = kv * c - base[NH * HD + d + 32] * sn;
    } else {
        qo = qv * c + base[d - 32] * sn;
        ko = kv * c + base[NH * HD + d - 32] * sn;
    }
    long out = ((long)(b * NH + h) * SEQ + s) * HD + d;
    q[out] = qo;
    k[out] = ko;
    v[out] = vv;
}

// ---------------- sliding-window attention, one (b,h,qtile) per CTA --------
__global__ __launch_bounds__(256) void attn_kernel(
    const float* __restrict__ q, const float* __restrict__ k,
    const float* __restrict__ v, float* __restrict__ o)
{
    extern __shared__ float sm[];
    float* Qs = sm;                       // QT*HD       = 4096
    float* Ks = Qs + QT * HD;             // KT*LDK      = 12480 (reused for V)
    float* Ss = Ks + KT * LDK;            // QT*KT       = 12288

    const int qt = blockIdx.x;
    const int h  = blockIdx.y;
    const int b  = blockIdx.z;
    const int i0 = qt * QT;
    const int j0 = i0 - WINDOW;
    const int tid = threadIdx.x;

    const float* Qg = q + ((long)(b * NH + h) * SEQ) * HD;
    const float* Kg = k + ((long)(b * NH + h) * SEQ) * HD;
    const float* Vg = v + ((long)(b * NH + h) * SEQ) * HD;

    // load Q tile (always in range)
    for (int f = tid; f < QT * HD / 4; f += 256) {
        float4 val = *(const float4*)(Qg + (long)i0 * HD + f * 4);
        *(float4*)(Qs + f * 4) = val;
    }
    // load K window with zero pad
    for (int f = tid; f < KT * HD / 4; f += 256) {
        int row = f / (HD / 4);
        int c4  = f % (HD / 4);
        int j = j0 + row;
        float4 val = make_float4(0.f, 0.f, 0.f, 0.f);
        if (j >= 0 && j < SEQ) val = *(const float4*)(Kg + (long)j * HD + c4 * 4);
        float* dst = Ks + row * LDK + c4 * 4;
        dst[0] = val.x; dst[1] = val.y; dst[2] = val.z; dst[3] = val.w;
    }
    __syncthreads();

    // S = Q K^T * scale, masked
    const float scale = 0.125f;  // HD^-0.5
    for (int p = tid; p < QT * KT; p += 256) {
        int qr = p / KT;
        int jr = p % KT;
        int j = j0 + jr;
        // |i - j| <= WINDOW  <=>  jr in [qr, qr+2*WINDOW]
        bool valid = (j >= 0) && (j < SEQ) && (jr >= qr) && (jr <= qr + 2 * WINDOW);
        float s = -INFINITY;
        if (valid) {
            float acc = 0.0f;
            const float* qrow = Qs + qr * HD;
            const float* krow = Ks + jr * LDK;
#pragma unroll
            for (int d = 0; d < HD; d++) acc = fmaf(qrow[d], krow[d], acc);
            s = acc * scale;
        }
        Ss[qr * KT + jr] = s;
    }
    __syncthreads();

    // softmax per row: warp w -> rows 8w..8w+7, lane handles 6 strided cols
    {
        int warp = tid >> 5, lane = tid & 31;
        for (int r = warp * 8; r < warp * 8 + 8; r++) {
            float* row = Ss + r * KT;
            float m = -INFINITY;
            for (int c = lane; c < KT; c += 32) m = fmaxf(m, row[c]);
#pragma unroll
            for (int off = 16; off > 0; off >>= 1)
                m = fmaxf(m, __shfl_xor_sync(0xffffffffu, m, off));
            float sum = 0.0f;
            for (int c = lane; c < KT; c += 32) {
                float e = __expf(row[c] - m);
                // -INF - m -> -INF -> exp 0; handle NaN safety for fully masked (can't happen)
                if (!isfinite(row[c])) e = 0.0f;
                row[c] = e;
                sum += e;
            }
#pragma unroll
            for (int off = 16; off > 0; off >>= 1)
                sum += __shfl_xor_sync(0xffffffffu, sum, off);
            float inv = 1.0f / sum;
            for (int c = lane; c < KT; c += 32) row[c] *= inv;
        }
    }
    __syncthreads();

    // overwrite Ks with V window
    for (int f = tid; f < KT * HD / 4; f += 256) {
        int row = f / (HD / 4);
        int c4  = f % (HD / 4);
        int j = j0 + row;
        float4 val = make_float4(0.f, 0.f, 0.f, 0.f);
        if (j >= 0 && j < SEQ) val = *(const float4*)(Vg + (long)j * HD + c4 * 4);
        float* dst = Ks + row * LDK + c4 * 4;
        dst[0] = val.x; dst[1] = val.y; dst[2] = val.z; dst[3] = val.w;
    }
    __syncthreads();

    // O = P V ; write to g_att[b, i, h*HD + d]
    for (int p = tid; p < QT * HD; p += 256) {
        int qr = p / HD;
        int d  = p % HD;
        float acc = 0.0f;
        const float* prow = Ss + qr * KT;
        const float* vcol = Ks + d;
#pragma unroll 4
        for (int j = 0; j < KT; j++) acc = fmaf(prow[j], vcol[j * LDK], acc);
        o[((long)(b * SEQ + i0 + qr)) * DIM + h * HD + d] = acc;
    }
}

// ---------------------------------------------------------------------------
extern "C" void kernel_launch(void* const* d_in, const int* in_sizes, int n_in,
                              void* d_out, int out_size)
{
    const float* hs   = (const float*)d_in[0];  // [2,2048,768]
    const float* Wqkv = (const float*)d_in[1];  // [768,2304]
    const float* Wo   = (const float*)d_in[2];  // [768,768]
    float* out = (float*)d_out;                 // [2,2048,768]

    float *qkv, *q, *k, *v, *att;
    cudaGetSymbolAddress((void**)&qkv, g_qkv);
    cudaGetSymbolAddress((void**)&q,   g_q);
    cudaGetSymbolAddress((void**)&k,   g_k);
    cudaGetSymbolAddress((void**)&v,   g_v);
    cudaGetSymbolAddress((void**)&att, g_att);

    // 1) QKV projection: [4096,768] @ [768,2304]
    {
        dim3 grid(3 * DIM / 128, BS * SEQ / 128);
        sgemm128<<<grid, 256>>>(hs, Wqkv, qkv, BS * SEQ, 3 * DIM, DIM);
    }

    // 2) RoPE + split to [b,h,s,d]
    {
        int total = BS * SEQ * NH * HD;
        rope_split<<<(total + 255) / 256, 256>>>(qkv, q, k, v);
    }

    // 3) sliding-window attention
    {
        int smem = (QT * HD + KT * LDK + QT * KT) * (int)sizeof(float);
        cudaFuncSetAttribute(attn_kernel, cudaFuncAttributeMaxDynamicSharedMemorySize, smem);
        dim3 grid(SEQ / QT, NH, BS);
        attn_kernel<<<grid, 256, smem>>>(q, k, v, att);
    }

    // 4) output projection: [4096,768] @ [768,768]
    {
        dim3 grid(DIM / 128, BS * SEQ / 128);
        sgemm128<<<grid, 256>>>(att, Wo, out, BS * SEQ, DIM, DIM);
    }
}

// round 2
// speedup vs baseline: 1.1241x; 1.1241x over previous
#include <cuda_runtime.h>
#include <cuda_bf16.h>
#include <mma.h>
#include <math.h>

using namespace nvcuda;

#define BS 2
#define SEQ 2048
#define DIM 768
#define NH 12
#define HD 64
#define WINDOW 64
#define ROPE_BASE 10000.0f

#define QT 64          // query tile
#define KT 192         // key window per tile: [i0-64, i0+127]
#define LDK 65         // padded K/V smem row stride (floats)

// GEMM tiling
#define BM 128
#define BN 128
#define BKK 32
#define LDA 36         // As row stride (floats), pad 4
#define LDB 132        // Bs row stride (floats), pad 4
#define GEMM_SMEM (2 * (BM * LDA + BKK * LDB) * (int)sizeof(float))  // 70656 B

// ---------------- scratch (static device memory; no allocs) ----------------
__device__ float g_qkv[BS * SEQ * 3 * DIM];          // [b, s, 3, nh, hd]
__device__ float g_q[BS * NH * SEQ * HD];            // [b, h, s, d]
__device__ float g_k[BS * NH * SEQ * HD];
__device__ float g_v[BS * NH * SEQ * HD];
__device__ float g_att[BS * SEQ * DIM];              // [b, s, h*HD + d]

// ---------------- tf32 WMMA GEMM: C[M,N] = A[M,K] @ B[K,N] -----------------
// 256 threads = 8 warps as 4(M) x 2(N); warp tile 32x64 = 2x4 wmma tiles.
__global__ __launch_bounds__(256) void gemm_tf32(
    const float* __restrict__ A, const float* __restrict__ B,
    float* __restrict__ C, int M, int N, int K)
{
    extern __shared__ float sm[];
    float* As[2] = { sm, sm + BM * LDA };
    float* Bs[2] = { sm + 2 * BM * LDA, sm + 2 * BM * LDA + BKK * LDB };

    const int tid  = threadIdx.x;
    const int warp = tid >> 5;
    const int wm   = warp >> 1;          // 0..3
    const int wn   = warp & 1;           // 0..1
    const int bm = blockIdx.y * BM;
    const int bn = blockIdx.x * BN;

    wmma::fragment<wmma::accumulator, 16, 16, 8, float> acc[2][4];
#pragma unroll
    for (int i = 0; i < 2; i++)
#pragma unroll
        for (int j = 0; j < 4; j++) wmma::fill_fragment(acc[i][j], 0.0f);

    // global->smem loaders (with RNA round to tf32)
    // A tile: BM x BKK ; thread t: row=t/8 (+32*r), col=(t%8)*4
    const int a_row = tid >> 3;
    const int a_col = (tid & 7) * 4;
    // B tile: BKK x BN ; thread t: row=t/32 (+8*r), col=(t%32)*4
    const int b_row = tid >> 5;
    const int b_col = (tid & 31) * 4;

    auto load_tile = [&](int k0, int buf) {
#pragma unroll
        for (int r = 0; r < 4; r++) {
            int row = a_row + r * 32;
            float4 v = *(const float4*)(A + (long)(bm + row) * K + k0 + a_col);
            float* dst = As[buf] + row * LDA + a_col;
            dst[0] = wmma::__float_to_tf32(v.x);
            dst[1] = wmma::__float_to_tf32(v.y);
            dst[2] = wmma::__float_to_tf32(v.z);
            dst[3] = wmma::__float_to_tf32(v.w);
        }
#pragma unroll
        for (int r = 0; r < 4; r++) {
            int row = b_row + r * 8;
            float4 v = *(const float4*)(B + (long)(k0 + row) * N + bn + b_col);
            float* dst = Bs[buf] + row * LDB + b_col;
            dst[0] = wmma::__float_to_tf32(v.x);
            dst[1] = wmma::__float_to_tf32(v.y);
            dst[2] = wmma::__float_to_tf32(v.z);
            dst[3] = wmma::__float_to_tf32(v.w);
        }
    };

    load_tile(0, 0);
    __syncthreads();

    int buf = 0;
    for (int k0 = 0; k0 < K; k0 += BKK) {
        if (k0 + BKK < K) load_tile(k0 + BKK, buf ^ 1);

#pragma unroll
        for (int kk = 0; kk < BKK; kk += 8) {
            wmma::fragment<wmma::matrix_a, 16, 16, 8, wmma::precision::tf32, wmma::row_major> af[2];
            wmma::fragment<wmma::matrix_b, 16, 16, 8, wmma::precision::tf32, wmma::row_major> bf[4];
#pragma unroll
            for (int i = 0; i < 2; i++)
                wmma::load_matrix_sync(af[i], As[buf] + (wm * 32 + i * 16) * LDA + kk, LDA);
#pragma unroll
            for (int j = 0; j < 4; j++)
                wmma::load_matrix_sync(bf[j], Bs[buf] + kk * LDB + wn * 64 + j * 16, LDB);
#pragma unroll
            for (int i = 0; i < 2; i++)
#pragma unroll
                for (int j = 0; j < 4; j++)
                    wmma::mma_sync(acc[i][j], af[i], bf[j], acc[i][j]);
        }
        __syncthreads();
        buf ^= 1;
    }

#pragma unroll
    for (int i = 0; i < 2; i++)
#pragma unroll
        for (int j = 0; j < 4; j++)
            wmma::store_matrix_sync(
                C + (long)(bm + wm * 32 + i * 16) * N + bn + wn * 64 + j * 16,
                acc[i][j], N, wmma::mem_row_major);
}

// ---------------- RoPE + split/transpose: qkv[b,s,3,h,d] -> q/k/v[b,h,s,d] --
__global__ void rope_split(const float* __restrict__ qkv,
                           float* __restrict__ q, float* __restrict__ k,
                           float* __restrict__ v)
{
    int idx = blockIdx.x * blockDim.x + threadIdx.x;
    const int total = BS * SEQ * NH * HD;
    if (idx >= total) return;
    int d = idx % HD;
    int h = (idx / HD) % NH;
    int s = (idx / (HD * NH)) % SEQ;
    int b = idx / (HD * NH * SEQ);

    const float* base = qkv + (((long)(b * SEQ + s) * 3) * NH + h) * HD;
    float qv = base[d];
    float kv = base[NH * HD + d];
    float vv = base[2 * NH * HD + d];

    int fi = d & 31;
    float inv_freq = expf(-(2.0f * (float)fi / (float)HD) * logf(ROPE_BASE));
    float angle = (float)s * inv_freq;
    float c = cosf(angle), sn = sinf(angle);

    float qo, ko;
    if (d < 32) {
        qo = qv * c - base[d + 32] * sn;
        ko = kv * c - base[NH * HD + d + 32] * sn;
    } else {
        qo = qv * c + base[d - 32] * sn;
        ko = kv * c + base[NH * HD + d - 32] * sn;
    }
    long out = ((long)(b * NH + h) * SEQ + s) * HD + d;
    q[out] = qo;
    k[out] = ko;
    v[out] = vv;
}

// ---------------- sliding-window attention, one (b,h,qtile) per CTA --------
__global__ __launch_bounds__(256) void attn_kernel(
    const float* __restrict__ q, const float* __restrict__ k,
    const float* __restrict__ v, float* __restrict__ o)
{
    extern __shared__ float smA[];
    float* Qs = smA;                      // QT*HD       = 4096
    float* Ks = Qs + QT * HD;             // KT*LDK      = 12480 (reused for V)
    float* Ss = Ks + KT * LDK;            // QT*KT       = 12288

    const int qt = blockIdx.x;
    const int h  = blockIdx.y;
    const int b  = blockIdx.z;
    const int i0 = qt * QT;
    const int j0 = i0 - WINDOW;
    const int tid = threadIdx.x;

    const float* Qg = q + ((long)(b * NH + h) * SEQ) * HD;
    const float* Kg = k + ((long)(b * NH + h) * SEQ) * HD;
    const float* Vg = v + ((long)(b * NH + h) * SEQ) * HD;

    for (int f = tid; f < QT * HD / 4; f += 256) {
        float4 val = *(const float4*)(Qg + (long)i0 * HD + f * 4);
        *(float4*)(Qs + f * 4) = val;
    }
    for (int f = tid; f < KT * HD / 4; f += 256) {
        int row = f / (HD / 4);
        int c4  = f % (HD / 4);
        int j = j0 + row;
        float4 val = make_float4(0.f, 0.f, 0.f, 0.f);
        if (j >= 0 && j < SEQ) val = *(const float4*)(Kg + (long)j * HD + c4 * 4);
        float* dst = Ks + row * LDK + c4 * 4;
        dst[0] = val.x; dst[1] = val.y; dst[2] = val.z; dst[3] = val.w;
    }
    __syncthreads();

    const float scale = 0.125f;
    for (int p = tid; p < QT * KT; p += 256) {
        int qr = p / KT;
        int jr = p % KT;
        int j = j0 + jr;
        bool valid = (j >= 0) && (j < SEQ) && (jr >= qr) && (jr <= qr + 2 * WINDOW);
        float s = -INFINITY;
        if (valid) {
            float acc = 0.0f;
            const float* qrow = Qs + qr * HD;
            const float* krow = Ks + jr * LDK;
#pragma unroll
            for (int d = 0; d < HD; d++) acc = fmaf(qrow[d], krow[d], acc);
            s = acc * scale;
        }
        Ss[qr * KT + jr] = s;
    }
    __syncthreads();

    {
        int warp = tid >> 5, lane = tid & 31;
        for (int r = warp * 8; r < warp * 8 + 8; r++) {
            float* row = Ss + r * KT;
            float m = -INFINITY;
            for (int c = lane; c < KT; c += 32) m = fmaxf(m, row[c]);
#pragma unroll
            for (int off = 16; off > 0; off >>= 1)
                m = fmaxf(m, __shfl_xor_sync(0xffffffffu, m, off));
            float sum = 0.0f;
            for (int c = lane; c < KT; c += 32) {
                float e = __expf(row[c] - m);
                if (!isfinite(row[c])) e = 0.0f;
                row[c] = e;
                sum += e;
            }
#pragma unroll
            for (int off = 16; off > 0; off >>= 1)
                sum += __shfl_xor_sync(0xffffffffu, sum, off);
            float inv = 1.0f / sum;
            for (int c = lane; c < KT; c += 32) row[c] *= inv;
        }
    }
    __syncthreads();

    for (int f = tid; f < KT * HD / 4; f += 256) {
        int row = f / (HD / 4);
        int c4  = f % (HD / 4);
        int j = j0 + row;
        float4 val = make_float4(0.f, 0.f, 0.f, 0.f);
        if (j >= 0 && j < SEQ) val = *(const float4*)(Vg + (long)j * HD + c4 * 4);
        float* dst = Ks + row * LDK + c4 * 4;
        dst[0] = val.x; dst[1] = val.y; dst[2] = val.z; dst[3] = val.w;
    }
    __syncthreads();

    for (int p = tid; p < QT * HD; p += 256) {
        int qr = p / HD;
        int d  = p % HD;
        float acc = 0.0f;
        const float* prow = Ss + qr * KT;
        const float* vcol = Ks + d;
#pragma unroll 4
        for (int j = 0; j < KT; j++) acc = fmaf(prow[j], vcol[j * LDK], acc);
        o[((long)(b * SEQ + i0 + qr)) * DIM + h * HD + d] = acc;
    }
}

// ---------------------------------------------------------------------------
extern "C" void kernel_launch(void* const* d_in, const int* in_sizes, int n_in,
                              void* d_out, int out_size)
{
    const float* hs   = (const float*)d_in[0];  // [2,2048,768]
    const float* Wqkv = (const float*)d_in[1];  // [768,2304]
    const float* Wo   = (const float*)d_in[2];  // [768,768]
    float* out = (float*)d_out;                 // [2,2048,768]

    float *qkv, *q, *k, *v, *att;
    cudaGetSymbolAddress((void**)&qkv, g_qkv);
    cudaGetSymbolAddress((void**)&q,   g_q);
    cudaGetSymbolAddress((void**)&k,   g_k);
    cudaGetSymbolAddress((void**)&v,   g_v);
    cudaGetSymbolAddress((void**)&att, g_att);

    static bool attr_set = false;
    if (!attr_set) {
        cudaFuncSetAttribute(gemm_tf32, cudaFuncAttributeMaxDynamicSharedMemorySize, GEMM_SMEM);
        int smem_attn = (QT * HD + KT * LDK + QT * KT) * (int)sizeof(float);
        cudaFuncSetAttribute(attn_kernel, cudaFuncAttributeMaxDynamicSharedMemorySize, smem_attn);
        attr_set = true;
    }

    // 1) QKV projection: [4096,768] @ [768,2304] (tf32 tensor cores)
    {
        dim3 grid(3 * DIM / BN, BS * SEQ / BM);
        gemm_tf32<<<grid, 256, GEMM_SMEM>>>(hs, Wqkv, qkv, BS * SEQ, 3 * DIM, DIM);
    }

    // 2) RoPE + split to [b,h,s,d]
    {
        int total = BS * SEQ * NH * HD;
        rope_split<<<(total + 255) / 256, 256>>>(qkv, q, k, v);
    }

    // 3) sliding-window attention
    {
        int smem_attn = (QT * HD + KT * LDK + QT * KT) * (int)sizeof(float);
        dim3 grid(SEQ / QT, NH, BS);
        attn_kernel<<<grid, 256, smem_attn>>>(q, k, v, att);
    }

    // 4) output projection: [4096,768] @ [768,768] (tf32 tensor cores)
    {
        dim3 grid(DIM / BN, BS * SEQ / BM);
        gemm_tf32<<<grid, 256, GEMM_SMEM>>>(att, Wo, out, BS * SEQ, DIM, DIM);
    }
}

// round 4
// speedup vs baseline: 1.4071x; 1.2517x over previous
#include <cuda_runtime.h>
#include <cuda_bf16.h>
#include <mma.h>
#include <math.h>
#include <stdint.h>

using namespace nvcuda;

#define BS 2
#define SEQ 2048
#define DIM 768
#define NH 12
#define HD 64
#define WINDOW 64
#define ROPE_BASE 10000.0f

#define QT 64          // query tile
#define KT 192         // key window per tile
#define LDK 65         // padded K/V smem row stride (floats)

#define MROWS 4096     // BS*SEQ
#define KDIM 768

// ---- GEMM tiling: CTA 128x128, 4 warps (2x2) of 64x64, BK=16, 3 stages ----
#define GBM 128
#define GBN 128
#define GBK 16
#define GSTG 3
#define LDT 20                              // smem row stride (floats): 16 + 4 pad (80B, 16B-aligned)
#define TILE_FLOATS (GBM * LDT)             // 2560 floats per matrix tile
#define STAGE_FLOATS (2 * TILE_FLOATS)      // 5120 floats = 20 KB
#define GEMM_SMEM (GSTG * STAGE_FLOATS * 4) // 61440 B
#define NKT (KDIM / GBK)                    // 48

// ---------------- scratch (static device memory; no allocs) ----------------
__device__ float g_qkv[MROWS * 3 * DIM];    // [b, s, 3, nh, hd]
__device__ float g_q[BS * NH * SEQ * HD];   // [b, h, s, d]
__device__ float g_k[BS * NH * SEQ * HD];
__device__ float g_v[BS * NH * SEQ * HD];
__device__ float g_hs_r[MROWS * DIM];       // tf32-rounded hidden states
__device__ float g_w1t[3 * DIM * DIM];      // Wqkv^T [2304,768], tf32-rounded
__device__ float g_wot[DIM * DIM];          // Wo^T   [768,768],  tf32-rounded
__device__ float g_att[MROWS * DIM];        // attention out, tf32-rounded

// ---------------- cp.async helpers -----------------------------------------
__device__ __forceinline__ uint32_t smem_u32(const void* p) {
    uint32_t a;
    asm("{ .reg .u64 t; cvta.to.shared.u64 t, %1; cvt.u32.u64 %0, t; }" : "=r"(a) : "l"(p));
    return a;
}
__device__ __forceinline__ void cp_async16(uint32_t dst, const void* src) {
    asm volatile("cp.async.cg.shared.global [%0], [%1], 16;" :: "r"(dst), "l"(src));
}
#define CP_COMMIT() asm volatile("cp.async.commit_group;" ::: "memory")
#define CP_WAIT(n)  asm volatile("cp.async.wait_group %0;" :: "n"(n) : "memory")

// ---------------- tf32 mma GEMM: C[M,N] = A[M,768] @ Bt[N,768]^T ------------
// A, Bt are tf32-pre-rounded fp32, K-major. 128 threads.
__global__ __launch_bounds__(128) void gemm_tf32(
    const float* __restrict__ A, const float* __restrict__ Bt,
    float* __restrict__ C, int N)
{
    extern __shared__ float sm[];
    const uint32_t sbase = smem_u32(sm);
    const int tid = threadIdx.x;
    const int warp = tid >> 5;
    const int wm = warp >> 1;                // 0..1
    const int wn = warp & 1;                 // 0..1
    const long bm = (long)blockIdx.y * GBM;
    const long bn = (long)blockIdx.x * GBN;

    wmma::fragment<wmma::accumulator, 16, 16, 8, float> acc[4][4];
#pragma unroll
    for (int i = 0; i < 4; i++)
#pragma unroll
        for (int j = 0; j < 4; j++) wmma::fill_fragment(acc[i][j], 0.0f);

    // stage loader: 1024 x 16B chunks (A: 512, B: 512); 8 per thread
    auto load_stage = [&](int buf, int k0) {
        uint32_t stage_base = sbase + (uint32_t)(buf * STAGE_FLOATS * 4);
#pragma unroll
        for (int it = 0; it < 8; it++) {
            int c = tid + it * 128;
            int mat = c >> 9;                 // 0 = A, 1 = B
            int row = (c >> 2) & 127;
            int ch  = c & 3;
            const float* g = (mat ? (Bt + (bn + row) * KDIM) : (A + (bm + row) * KDIM))
                             + k0 + ch * 4;
            uint32_t dst = stage_base + (uint32_t)((mat * TILE_FLOATS + row * LDT + ch * 4) * 4);
            cp_async16(dst, g);
        }
    };

    // prologue: stages 0..GSTG-2
    load_stage(0, 0);
    CP_COMMIT();
    load_stage(1, GBK);
    CP_COMMIT();

#pragma unroll 1
    for (int kt = 0; kt < NKT; kt++) {
        CP_WAIT(GSTG - 2);
        __syncthreads();

        int nxt = kt + GSTG - 1;
        if (nxt < NKT) load_stage(nxt % GSTG, nxt * GBK);
        CP_COMMIT();

        const float* As = sm + (kt % GSTG) * STAGE_FLOATS;
        const float* Bs = As + TILE_FLOATS;
#pragma unroll
        for (int kk = 0; kk < GBK; kk += 8) {
            wmma::fragment<wmma::matrix_a, 16, 16, 8, wmma::precision::tf32, wmma::row_major> af[4];
            wmma::fragment<wmma::matrix_b, 16, 16, 8, wmma::precision::tf32, wmma::col_major> bf[4];
#pragma unroll
            for (int i = 0; i < 4; i++)
                wmma::load_matrix_sync(af[i], As + (wm * 64 + i * 16) * LDT + kk, LDT);
#pragma unroll
            for (int j = 0; j < 4; j++)
                wmma::load_matrix_sync(bf[j], Bs + (wn * 64 + j * 16) * LDT + kk, LDT);
#pragma unroll
            for (int i = 0; i < 4; i++)
#pragma unroll
                for (int j = 0; j < 4; j++)
                    wmma::mma_sync(acc[i][j], af[i], bf[j], acc[i][j]);
        }
    }

#pragma unroll
    for (int i = 0; i < 4; i++)
#pragma unroll
        for (int j = 0; j < 4; j++)
            wmma::store_matrix_sync(
                C + (bm + wm * 64 + i * 16) * N + bn + wn * 64 + j * 16,
                acc[i][j], N, wmma::mem_row_major);
}

// ---------------- tf32 pre-rounding ------------------------------------------
__global__ void round_tf32(const float4* __restrict__ src, float4* __restrict__ dst, int n4)
{
    int i = blockIdx.x * blockDim.x + threadIdx.x;
    if (i >= n4) return;
    float4 x = src[i];
    x.x = wmma::__float_to_tf32(x.x);
    x.y = wmma::__float_to_tf32(x.y);
    x.z = wmma::__float_to_tf32(x.z);
    x.w = wmma::__float_to_tf32(x.w);
    dst[i] = x;
}

// src [Kd, Nd] fp32 -> dst [Nd, Kd] tf32-rounded (transpose + round)
__global__ void transpose_round(const float* __restrict__ src, float* __restrict__ dst,
                                int Kd, int Nd)
{
    __shared__ float t[32][33];
    int n0 = blockIdx.x * 32, k0 = blockIdx.y * 32;
    int tx = threadIdx.x, ty = threadIdx.y;
#pragma unroll
    for (int r = 0; r < 4; r++)
        t[ty + r * 8][tx] = src[(size_t)(k0 + ty + r * 8) * Nd + n0 + tx];
    __syncthreads();
#pragma unroll
    for (int r = 0; r < 4; r++)
        dst[(size_t)(n0 + ty + r * 8) * Kd + k0 + tx] = wmma::__float_to_tf32(t[tx][ty + r * 8]);
}

// ---------------- RoPE + split/transpose: qkv[b,s,3,h,d] -> q/k/v[b,h,s,d] --
__global__ void rope_split(const float* __restrict__ qkv,
                           float* __restrict__ q, float* __restrict__ k,
                           float* __restrict__ v)
{
    int idx = blockIdx.x * blockDim.x + threadIdx.x;
    const int total = BS * SEQ * NH * HD;
    if (idx >= total) return;
    int d = idx % HD;
    int h = (idx / HD) % NH;
    int s = (idx / (HD * NH)) % SEQ;
    int b = idx / (HD * NH * SEQ);

    const float* base = qkv + (((long)(b * SEQ + s) * 3) * NH + h) * HD;
    float qv = base[d];
    float kv = base[NH * HD + d];
    float vv = base[2 * NH * HD + d];

    int fi = d & 31;
    float inv_freq = expf(-(2.0f * (float)fi / (float)HD) * logf(ROPE_BASE));
    float angle = (float)s * inv_freq;
    float c = cosf(angle), sn = sinf(angle);

    float qo, ko;
    if (d < 32) {
        qo = qv * c - base[d + 32] * sn;
        ko = kv * c - base[NH * HD + d + 32] * sn;
    } else {
        qo = qv * c + base[d - 32] * sn;
        ko = kv * c + base[NH * HD + d - 32] * sn;
    }
    long out = ((long)(b * NH + h) * SEQ + s) * HD + d;
    q[out] = qo;
    k[out] = ko;
    v[out] = vv;
}

// ---------------- sliding-window attention (fp32, tf32-rounded output) ------
__global__ __launch_bounds__(256) void attn_kernel(
    const float* __restrict__ q, const float* __restrict__ k,
    const float* __restrict__ v, float* __restrict__ o)
{
    extern __shared__ float smA[];
    float* Qs = smA;                      // QT*HD
    float* Ks = Qs + QT * HD;             // KT*LDK (reused for V)
    float* Ss = Ks + KT * LDK;            // QT*KT

    const int qt = blockIdx.x;
    const int h  = blockIdx.y;
    const int b  = blockIdx.z;
    const int i0 = qt * QT;
    const int j0 = i0 - WINDOW;
    const int tid = threadIdx.x;

    const float* Qg = q + ((long)(b * NH + h) * SEQ) * HD;
    const float* Kg = k + ((long)(b * NH + h) * SEQ) * HD;
    const float* Vg = v + ((long)(b * NH + h) * SEQ) * HD;

    for (int f = tid; f < QT * HD / 4; f += 256) {
        float4 val = *(const float4*)(Qg + (long)i0 * HD + f * 4);
        *(float4*)(Qs + f * 4) = val;
    }
    for (int f = tid; f < KT * HD / 4; f += 256) {
        int row = f / (HD / 4);
        int c4  = f % (HD / 4);
        int j = j0 + row;
        float4 val = make_float4(0.f, 0.f, 0.f, 0.f);
        if (j >= 0 && j < SEQ) val = *(const float4*)(Kg + (long)j * HD + c4 * 4);
        float* dst = Ks + row * LDK + c4 * 4;
        dst[0] = val.x; dst[1] = val.y; dst[2] = val.z; dst[3] = val.w;
    }
    __syncthreads();

    const float scale = 0.125f;
    for (int p = tid; p < QT * KT; p += 256) {
        int qr = p / KT;
        int jr = p % KT;
        int j = j0 + jr;
        bool valid = (j >= 0) && (j < SEQ) && (jr >= qr) && (jr <= qr + 2 * WINDOW);
        float s = -INFINITY;
        if (valid) {
            float acc = 0.0f;
            const float* qrow = Qs + qr * HD;
            const float* krow = Ks + jr * LDK;
#pragma unroll
            for (int d = 0; d < HD; d++) acc = fmaf(qrow[d], krow[d], acc);
            s = acc * scale;
        }
        Ss[qr * KT + jr] = s;
    }
    __syncthreads();

    {
        int warp = tid >> 5, lane = tid & 31;
        for (int r = warp * 8; r < warp * 8 + 8; r++) {
            float* row = Ss + r * KT;
            float m = -INFINITY;
            for (int c = lane; c < KT; c += 32) m = fmaxf(m, row[c]);
#pragma unroll
            for (int off = 16; off > 0; off >>= 1)
                m = fmaxf(m, __shfl_xor_sync(0xffffffffu, m, off));
            float sum = 0.0f;
            for (int c = lane; c < KT; c += 32) {
                float e = __expf(row[c] - m);
                if (!isfinite(row[c])) e = 0.0f;
                row[c] = e;
                sum += e;
            }
#pragma unroll
            for (int off = 16; off > 0; off >>= 1)
                sum += __shfl_xor_sync(0xffffffffu, sum, off);
            float inv = 1.0f / sum;
            for (int c = lane; c < KT; c += 32) row[c] *= inv;
        }
    }
    __syncthreads();

    for (int f = tid; f < KT * HD / 4; f += 256) {
        int row = f / (HD / 4);
        int c4  = f % (HD / 4);
        int j = j0 + row;
        float4 val = make_float4(0.f, 0.f, 0.f, 0.f);
        if (j >= 0 && j < SEQ) val = *(const float4*)(Vg + (long)j * HD + c4 * 4);
        float* dst = Ks + row * LDK + c4 * 4;
        dst[0] = val.x; dst[1] = val.y; dst[2] = val.z; dst[3] = val.w;
    }
    __syncthreads();

    for (int p = tid; p < QT * HD; p += 256) {
        int qr = p / HD;
        int d  = p % HD;
        float acc = 0.0f;
        const float* prow = Ss + qr * KT;
        const float* vcol = Ks + d;
#pragma unroll 4
        for (int j = 0; j < KT; j++) acc = fmaf(prow[j], vcol[j * LDK], acc);
        o[((long)(b * SEQ + i0 + qr)) * DIM + h * HD + d] = wmma::__float_to_tf32(acc);
    }
}

// ---------------------------------------------------------------------------
extern "C" void kernel_launch(void* const* d_in, const int* in_sizes, int n_in,
                              void* d_out, int out_size)
{
    const float* hs   = (const float*)d_in[0];  // [2,2048,768]
    const float* Wqkv = (const float*)d_in[1];  // [768,2304]
    const float* Wo   = (const float*)d_in[2];  // [768,768]
    float* out = (float*)d_out;                 // [2,2048,768]

    float *qkv, *q, *k, *v, *hs_r, *w1t, *wot, *att;
    cudaGetSymbolAddress((void**)&qkv,  g_qkv);
    cudaGetSymbolAddress((void**)&q,    g_q);
    cudaGetSymbolAddress((void**)&k,    g_k);
    cudaGetSymbolAddress((void**)&v,    g_v);
    cudaGetSymbolAddress((void**)&hs_r, g_hs_r);
    cudaGetSymbolAddress((void**)&w1t,  g_w1t);
    cudaGetSymbolAddress((void**)&wot,  g_wot);
    cudaGetSymbolAddress((void**)&att,  g_att);

    cudaFuncSetAttribute(gemm_tf32, cudaFuncAttributeMaxDynamicSharedMemorySize, GEMM_SMEM);
    int smem_attn = (QT * HD + KT * LDK + QT * KT) * (int)sizeof(float);
    cudaFuncSetAttribute(attn_kernel, cudaFuncAttributeMaxDynamicSharedMemorySize, smem_attn);

    // 0) pre-round inputs to tf32 (weights also transposed to [N,K])
    {
        int n4 = MROWS * DIM / 4;
        round_tf32<<<(n4 + 255) / 256, 256>>>((const float4*)hs, (float4*)hs_r, n4);
        transpose_round<<<dim3(3 * DIM / 32, DIM / 32), dim3(32, 8)>>>(Wqkv, w1t, DIM, 3 * DIM);
        transpose_round<<<dim3(DIM / 32, DIM / 32), dim3(32, 8)>>>(Wo, wot, DIM, DIM);
    }

    // 1) QKV projection: [4096,768] @ [768,2304]
    gemm_tf32<<<dim3(3 * DIM / GBN, MROWS / GBM), 128, GEMM_SMEM>>>(hs_r, w1t, qkv, 3 * DIM);

    // 2) RoPE + split to [b,h,s,d]
    {
        int total = BS * SEQ * NH * HD;
        rope_split<<<(total + 255) / 256, 256>>>(qkv, q, k, v);
    }

    // 3) sliding-window attention (emits tf32-rounded values)
    {
        dim3 grid(SEQ / QT, NH, BS);
        attn_kernel<<<grid, 256, smem_attn>>>(q, k, v, att);
    }

    // 4) output projection: [4096,768] @ [768,768]
    gemm_tf32<<<dim3(DIM / GBN, MROWS / GBM), 128, GEMM_SMEM>>>(att, wot, out, DIM);
}

// round 5
// speedup vs baseline: 1.9179x; 1.3630x over previous
#include <cuda_runtime.h>
#include <cuda_bf16.h>
#include <mma.h>
#include <math.h>
#include <stdint.h>

using namespace nvcuda;

#define BS 2
#define SEQ 2048
#define DIM 768
#define NH 12
#define HD 64
#define WINDOW 64
#define ROPE_BASE 10000.0f

#define QT 64          // query tile
#define KT 192         // key window per tile
#define LDK 65         // padded K/V smem row stride (floats, odd -> conflict-light)

#define MROWS 4096     // BS*SEQ
#define KDIM 768

// ---- GEMM tiling: CTA 128x128, 4 warps (2x2) of 64x64, BK=16, 3 stages ----
#define GBM 128
#define GBN 128
#define GBK 16
#define GSTG 3
#define LDT 20
#define TILE_FLOATS (GBM * LDT)
#define STAGE_FLOATS (2 * TILE_FLOATS)
#define GEMM_SMEM (GSTG * STAGE_FLOATS * 4)
#define NKT (KDIM / GBK)

// ---------------- scratch (static device memory; no allocs) ----------------
__device__ float g_qkv[MROWS * 3 * DIM];
__device__ float g_q[BS * NH * SEQ * HD];
__device__ float g_k[BS * NH * SEQ * HD];
__device__ float g_v[BS * NH * SEQ * HD];
__device__ float g_hs_r[MROWS * DIM];
__device__ float g_w1t[3 * DIM * DIM];
__device__ float g_wot[DIM * DIM];
__device__ float g_att[MROWS * DIM];

// ---------------- cp.async helpers -----------------------------------------
__device__ __forceinline__ uint32_t smem_u32(const void* p) {
    uint32_t a;
    asm("{ .reg .u64 t; cvta.to.shared.u64 t, %1; cvt.u32.u64 %0, t; }" : "=r"(a) : "l"(p));
    return a;
}
__device__ __forceinline__ void cp_async16(uint32_t dst, const void* src) {
    asm volatile("cp.async.cg.shared.global [%0], [%1], 16;" :: "r"(dst), "l"(src));
}
#define CP_COMMIT() asm volatile("cp.async.commit_group;" ::: "memory")
#define CP_WAIT(n)  asm volatile("cp.async.wait_group %0;" :: "n"(n) : "memory")

// ---------------- tf32 mma GEMM: C[M,N] = A[M,768] @ Bt[N,768]^T ------------
__global__ __launch_bounds__(128) void gemm_tf32(
    const float* __restrict__ A, const float* __restrict__ Bt,
    float* __restrict__ C, int N)
{
    extern __shared__ float sm[];
    const uint32_t sbase = smem_u32(sm);
    const int tid = threadIdx.x;
    const int warp = tid >> 5;
    const int wm = warp >> 1;
    const int wn = warp & 1;
    const long bm = (long)blockIdx.y * GBM;
    const long bn = (long)blockIdx.x * GBN;

    wmma::fragment<wmma::accumulator, 16, 16, 8, float> acc[4][4];
#pragma unroll
    for (int i = 0; i < 4; i++)
#pragma unroll
        for (int j = 0; j < 4; j++) wmma::fill_fragment(acc[i][j], 0.0f);

    auto load_stage = [&](int buf, int k0) {
        uint32_t stage_base = sbase + (uint32_t)(buf * STAGE_FLOATS * 4);
#pragma unroll
        for (int it = 0; it < 8; it++) {
            int c = tid + it * 128;
            int mat = c >> 9;
            int row = (c >> 2) & 127;
            int ch  = c & 3;
            const float* g = (mat ? (Bt + (bn + row) * KDIM) : (A + (bm + row) * KDIM))
                             + k0 + ch * 4;
            uint32_t dst = stage_base + (uint32_t)((mat * TILE_FLOATS + row * LDT + ch * 4) * 4);
            cp_async16(dst, g);
        }
    };

    load_stage(0, 0);
    CP_COMMIT();
    load_stage(1, GBK);
    CP_COMMIT();

#pragma unroll 1
    for (int kt = 0; kt < NKT; kt++) {
        CP_WAIT(GSTG - 2);
        __syncthreads();

        int nxt = kt + GSTG - 1;
        if (nxt < NKT) load_stage(nxt % GSTG, nxt * GBK);
        CP_COMMIT();

        const float* As = sm + (kt % GSTG) * STAGE_FLOATS;
        const float* Bs = As + TILE_FLOATS;
#pragma unroll
        for (int kk = 0; kk < GBK; kk += 8) {
            wmma::fragment<wmma::matrix_a, 16, 16, 8, wmma::precision::tf32, wmma::row_major> af[4];
            wmma::fragment<wmma::matrix_b, 16, 16, 8, wmma::precision::tf32, wmma::col_major> bf[4];
#pragma unroll
            for (int i = 0; i < 4; i++)
                wmma::load_matrix_sync(af[i], As + (wm * 64 + i * 16) * LDT + kk, LDT);
#pragma unroll
            for (int j = 0; j < 4; j++)
                wmma::load_matrix_sync(bf[j], Bs + (wn * 64 + j * 16) * LDT + kk, LDT);
#pragma unroll
            for (int i = 0; i < 4; i++)
#pragma unroll
                for (int j = 0; j < 4; j++)
                    wmma::mma_sync(acc[i][j], af[i], bf[j], acc[i][j]);
        }
    }

#pragma unroll
    for (int i = 0; i < 4; i++)
#pragma unroll
        for (int j = 0; j < 4; j++)
            wmma::store_matrix_sync(
                C + (bm + wm * 64 + i * 16) * N + bn + wn * 64 + j * 16,
                acc[i][j], N, wmma::mem_row_major);
}

// ---------------- tf32 pre-rounding -----------------------------------------
__global__ void round_tf32(const float4* __restrict__ src, float4* __restrict__ dst, int n4)
{
    int i = blockIdx.x * blockDim.x + threadIdx.x;
    if (i >= n4) return;
    float4 x = src[i];
    x.x = wmma::__float_to_tf32(x.x);
    x.y = wmma::__float_to_tf32(x.y);
    x.z = wmma::__float_to_tf32(x.z);
    x.w = wmma::__float_to_tf32(x.w);
    dst[i] = x;
}

__global__ void transpose_round(const float* __restrict__ src, float* __restrict__ dst,
                                int Kd, int Nd)
{
    __shared__ float t[32][33];
    int n0 = blockIdx.x * 32, k0 = blockIdx.y * 32;
    int tx = threadIdx.x, ty = threadIdx.y;
#pragma unroll
    for (int r = 0; r < 4; r++)
        t[ty + r * 8][tx] = src[(size_t)(k0 + ty + r * 8) * Nd + n0 + tx];
    __syncthreads();
#pragma unroll
    for (int r = 0; r < 4; r++)
        dst[(size_t)(n0 + ty + r * 8) * Kd + k0 + tx] = wmma::__float_to_tf32(t[tx][ty + r * 8]);
}

// ---------------- RoPE + split/transpose ------------------------------------
__global__ void rope_split(const float* __restrict__ qkv,
                           float* __restrict__ q, float* __restrict__ k,
                           float* __restrict__ v)
{
    int idx = blockIdx.x * blockDim.x + threadIdx.x;
    const int total = BS * SEQ * NH * HD;
    if (idx >= total) return;
    int d = idx % HD;
    int h = (idx / HD) % NH;
    int s = (idx / (HD * NH)) % SEQ;
    int b = idx / (HD * NH * SEQ);

    const float* base = qkv + (((long)(b * SEQ + s) * 3) * NH + h) * HD;
    float qv = base[d];
    float kv = base[NH * HD + d];
    float vv = base[2 * NH * HD + d];

    int fi = d & 31;
    float inv_freq = expf(-(2.0f * (float)fi / (float)HD) * logf(ROPE_BASE));
    float angle = (float)s * inv_freq;
    float c = cosf(angle), sn = sinf(angle);

    float qo, ko;
    if (d < 32) {
        qo = qv * c - base[d + 32] * sn;
        ko = kv * c - base[NH * HD + d + 32] * sn;
    } else {
        qo = qv * c + base[d - 32] * sn;
        ko = kv * c + base[NH * HD + d - 32] * sn;
    }
    long out = ((long)(b * NH + h) * SEQ + s) * HD + d;
    q[out] = qo;
    k[out] = ko;
    v[out] = vv;
}

// ---------------- sliding-window attention (register-blocked) ---------------
__global__ __launch_bounds__(256) void attn_kernel(
    const float* __restrict__ q, const float* __restrict__ k,
    const float* __restrict__ v, float* __restrict__ o)
{
    extern __shared__ float smA[];
    float* Qs = smA;                      // QT*HD
    float* Ks = Qs + QT * HD;             // KT*LDK (reused for V)
    float* Ss = Ks + KT * LDK;            // QT*KT

    const int qt = blockIdx.x;
    const int h  = blockIdx.y;
    const int b  = blockIdx.z;
    const int i0 = qt * QT;
    const int j0 = i0 - WINDOW;
    const int tid = threadIdx.x;

    const float* Qg = q + ((long)(b * NH + h) * SEQ) * HD;
    const float* Kg = k + ((long)(b * NH + h) * SEQ) * HD;
    const float* Vg = v + ((long)(b * NH + h) * SEQ) * HD;

    for (int f = tid; f < QT * HD / 4; f += 256) {
        float4 val = *(const float4*)(Qg + (long)i0 * HD + f * 4);
        *(float4*)(Qs + f * 4) = val;
    }
    for (int f = tid; f < KT * HD / 4; f += 256) {
        int row = f / (HD / 4);
        int c4  = f % (HD / 4);
        int j = j0 + row;
        float4 val = make_float4(0.f, 0.f, 0.f, 0.f);
        if (j >= 0 && j < SEQ) val = *(const float4*)(Kg + (long)j * HD + c4 * 4);
        float* dst = Ks + row * LDK + c4 * 4;
        dst[0] = val.x; dst[1] = val.y; dst[2] = val.z; dst[3] = val.w;
    }
    __syncthreads();

    // ---- S = Q K^T * scale (register-blocked 8q x 6j per thread) ----
    const float scale = 0.125f;
    {
        const int tq0 = (tid >> 5) * 8;        // warp -> 8 query rows
        const int jr0 = (tid & 31) * 6;        // lane -> 6 contiguous keys
        // window validity for this block: jr in [qr, qr+128]
        bool block_dead = (jr0 + 5 < tq0) || (jr0 > tq0 + 7 + 2 * WINDOW);

        float acc[8][6];
        if (!block_dead) {
#pragma unroll
            for (int i = 0; i < 8; i++)
#pragma unroll
                for (int j = 0; j < 6; j++) acc[i][j] = 0.0f;
#pragma unroll 4
            for (int d = 0; d < HD; d++) {
                float qv[8], kv[6];
#pragma unroll
                for (int i = 0; i < 8; i++) qv[i] = Qs[(tq0 + i) * HD + d];
#pragma unroll
                for (int j = 0; j < 6; j++) kv[j] = Ks[(jr0 + j) * LDK + d];
#pragma unroll
                for (int i = 0; i < 8; i++)
#pragma unroll
                    for (int j = 0; j < 6; j++)
                        acc[i][j] = fmaf(qv[i], kv[j], acc[i][j]);
            }
        }
#pragma unroll
        for (int i = 0; i < 8; i++) {
            int qr = tq0 + i;
#pragma unroll
            for (int j = 0; j < 6; j++) {
                int jr = jr0 + j;
                int jg = j0 + jr;
                bool valid = !block_dead && (jg >= 0) && (jg < SEQ) &&
                             (jr >= qr) && (jr <= qr + 2 * WINDOW);
                Ss[qr * KT + jr] = valid ? acc[i][j] * scale : -INFINITY;
            }
        }
    }
    __syncthreads();

    // ---- softmax per row ----
    {
        int warp = tid >> 5, lane = tid & 31;
        for (int r = warp * 8; r < warp * 8 + 8; r++) {
            float* row = Ss + r * KT;
            float m = -INFINITY;
            for (int c = lane; c < KT; c += 32) m = fmaxf(m, row[c]);
#pragma unroll
            for (int off = 16; off > 0; off >>= 1)
                m = fmaxf(m, __shfl_xor_sync(0xffffffffu, m, off));
            float sum = 0.0f;
            for (int c = lane; c < KT; c += 32) {
                float e = __expf(row[c] - m);
                if (!isfinite(row[c])) e = 0.0f;
                row[c] = e;
                sum += e;
            }
#pragma unroll
            for (int off = 16; off > 0; off >>= 1)
                sum += __shfl_xor_sync(0xffffffffu, sum, off);
            float inv = 1.0f / sum;
            for (int c = lane; c < KT; c += 32) row[c] *= inv;
        }
    }
    __syncthreads();

    // ---- load V window (reuse Ks) ----
    for (int f = tid; f < KT * HD / 4; f += 256) {
        int row = f / (HD / 4);
        int c4  = f % (HD / 4);
        int j = j0 + row;
        float4 val = make_float4(0.f, 0.f, 0.f, 0.f);
        if (j >= 0 && j < SEQ) val = *(const float4*)(Vg + (long)j * HD + c4 * 4);
        float* dst = Ks + row * LDK + c4 * 4;
        dst[0] = val.x; dst[1] = val.y; dst[2] = val.z; dst[3] = val.w;
    }
    __syncthreads();

    // ---- O = P V (register-blocked 4q x 4d per thread) ----
    {
        const int qr0 = (tid >> 4) * 4;        // 16 groups of 4 query rows
        const int d0  = (tid & 15) * 4;        // 16 groups of 4 dims
        float acc[4][4];
#pragma unroll
        for (int i = 0; i < 4; i++)
#pragma unroll
            for (int j = 0; j < 4; j++) acc[i][j] = 0.0f;

        // only j in [qr0, qr0+3+128] can contribute (probs are 0 outside)
        const int jlo = qr0;
        const int jhi = qr0 + 3 + 2 * WINDOW;  // inclusive
#pragma unroll 2
        for (int j = jlo; j <= (jhi < KT - 1 ? jhi : KT - 1); j++) {
            float vv[4], pv[4];
            const float* vrow = Ks + j * LDK + d0;
#pragma unroll
            for (int t = 0; t < 4; t++) vv[t] = vrow[t];
#pragma unroll
            for (int i = 0; i < 4; i++) pv[i] = Ss[(qr0 + i) * KT + j];
#pragma unroll
            for (int i = 0; i < 4; i++)
#pragma unroll
                for (int t = 0; t < 4; t++)
                    acc[i][t] = fmaf(pv[i], vv[t], acc[i][t]);
        }
#pragma unroll
        for (int i = 0; i < 4; i++) {
            long orow = ((long)(b * SEQ + i0 + qr0 + i)) * DIM + h * HD + d0;
            float4 f = make_float4(wmma::__float_to_tf32(acc[i][0]),
                                   wmma::__float_to_tf32(acc[i][1]),
                                   wmma::__float_to_tf32(acc[i][2]),
                                   wmma::__float_to_tf32(acc[i][3]));
            *(float4*)(o + orow) = f;
        }
    }
}

// ---------------------------------------------------------------------------
extern "C" void kernel_launch(void* const* d_in, const int* in_sizes, int n_in,
                              void* d_out, int out_size)
{
    const float* hs   = (const float*)d_in[0];
    const float* Wqkv = (const float*)d_in[1];
    const float* Wo   = (const float*)d_in[2];
    float* out = (float*)d_out;

    float *qkv, *q, *k, *v, *hs_r, *w1t, *wot, *att;
    cudaGetSymbolAddress((void**)&qkv,  g_qkv);
    cudaGetSymbolAddress((void**)&q,    g_q);
    cudaGetSymbolAddress((void**)&k,    g_k);
    cudaGetSymbolAddress((void**)&v,    g_v);
    cudaGetSymbolAddress((void**)&hs_r, g_hs_r);
    cudaGetSymbolAddress((void**)&w1t,  g_w1t);
    cudaGetSymbolAddress((void**)&wot,  g_wot);
    cudaGetSymbolAddress((void**)&att,  g_att);

    cudaFuncSetAttribute(gemm_tf32, cudaFuncAttributeMaxDynamicSharedMemorySize, GEMM_SMEM);
    int smem_attn = (QT * HD + KT * LDK + QT * KT) * (int)sizeof(float);
    cudaFuncSetAttribute(attn_kernel, cudaFuncAttributeMaxDynamicSharedMemorySize, smem_attn);

    // 0) pre-round inputs to tf32
    {
        int n4 = MROWS * DIM / 4;
        round_tf32<<<(n4 + 255) / 256, 256>>>((const float4*)hs, (float4*)hs_r, n4);
        transpose_round<<<dim3(3 * DIM / 32, DIM / 32), dim3(32, 8)>>>(Wqkv, w1t, DIM, 3 * DIM);
        transpose_round<<<dim3(DIM / 32, DIM / 32), dim3(32, 8)>>>(Wo, wot, DIM, DIM);
    }

    // 1) QKV projection
    gemm_tf32<<<dim3(3 * DIM / GBN, MROWS / GBM), 128, GEMM_SMEM>>>(hs_r, w1t, qkv, 3 * DIM);

    // 2) RoPE + split
    {
        int total = BS * SEQ * NH * HD;
        rope_split<<<(total + 255) / 256, 256>>>(qkv, q, k, v);
    }

    // 3) sliding-window attention
    {
        dim3 grid(SEQ / QT, NH, BS);
        attn_kernel<<<grid, 256, smem_attn>>>(q, k, v, att);
    }

    // 4) output projection
    gemm_tf32<<<dim3(DIM / GBN, MROWS / GBM), 128, GEMM_SMEM>>>(att, wot, out, DIM);
}

// round 6
// speedup vs baseline: 3.8244x; 1.9940x over previous
#include <cuda_runtime.h>
#include <cuda_fp16.h>
#include <mma.h>
#include <math.h>
#include <stdint.h>

using namespace nvcuda;

#define BS 2
#define SEQ 2048
#define DIM 768
#define NH 12
#define HD 64
#define WINDOW 64
#define ROPE_BASE 10000.0f

#define QT 64          // query tile
#define KT 192         // key window per tile
#define LDK 65         // padded K/V smem row stride (floats)

#define MROWS 4096     // BS*SEQ
#define KDIM 768

// ---- GEMM tiling: CTA 128x128, 4 warps (2x2) of 64x64, BK=32 fp16, 3 stages
#define GBM 128
#define GBN 128
#define GBK 32
#define GSTG 3
#define LDT 40                               // smem row stride (halfs): 32 + 8 pad (80B)
#define TILE_HALFS (GBM * LDT)               // 5120 halfs per matrix tile
#define STAGE_HALFS (2 * TILE_HALFS)         // 10240 halfs = 20 KB
#define GEMM_SMEM (GSTG * STAGE_HALFS * 2)   // 61440 B
#define NKT (KDIM / GBK)                     // 24

// ---------------- scratch (static device memory; no allocs) ----------------
__device__ float  g_qkv[MROWS * 3 * DIM];
__device__ float  g_q[BS * NH * SEQ * HD];
__device__ float  g_k[BS * NH * SEQ * HD];
__device__ float  g_v[BS * NH * SEQ * HD];
__device__ __half g_hs_h[MROWS * DIM];       // fp16 hidden states
__device__ __half g_w1t[3 * DIM * DIM];      // Wqkv^T [2304,768] fp16
__device__ __half g_wot[DIM * DIM];          // Wo^T   [768,768]  fp16
__device__ __half g_att[MROWS * DIM];        // attention out fp16

// ---------------- cp.async helpers -----------------------------------------
__device__ __forceinline__ uint32_t smem_u32(const void* p) {
    uint32_t a;
    asm("{ .reg .u64 t; cvta.to.shared.u64 t, %1; cvt.u32.u64 %0, t; }" : "=r"(a) : "l"(p));
    return a;
}
__device__ __forceinline__ void cp_async16(uint32_t dst, const void* src) {
    asm volatile("cp.async.cg.shared.global [%0], [%1], 16;" :: "r"(dst), "l"(src));
}
#define CP_COMMIT() asm volatile("cp.async.commit_group;" ::: "memory")
#define CP_WAIT(n)  asm volatile("cp.async.wait_group %0;" :: "n"(n) : "memory")

// ---------------- fp16 mma GEMM: C[M,N] = A[M,768] @ Bt[N,768]^T ------------
// A, Bt fp16 K-major. 128 threads, fp32 accumulate.
__global__ __launch_bounds__(128) void gemm_f16(
    const __half* __restrict__ A, const __half* __restrict__ Bt,
    float* __restrict__ C, int N)
{
    extern __shared__ __half sm[];
    const uint32_t sbase = smem_u32(sm);
    const int tid = threadIdx.x;
    const int warp = tid >> 5;
    const int wm = warp >> 1;
    const int wn = warp & 1;
    const long bm = (long)blockIdx.y * GBM;
    const long bn = (long)blockIdx.x * GBN;

    wmma::fragment<wmma::accumulator, 16, 16, 16, float> acc[4][4];
#pragma unroll
    for (int i = 0; i < 4; i++)
#pragma unroll
        for (int j = 0; j < 4; j++) wmma::fill_fragment(acc[i][j], 0.0f);

    // stage loader: A rows 128 x (32 halfs = 64B = 4x16B), B same: 1024 chunks
    auto load_stage = [&](int buf, int k0) {
        uint32_t stage_base = sbase + (uint32_t)(buf * STAGE_HALFS * 2);
#pragma unroll
        for (int it = 0; it < 8; it++) {
            int c = tid + it * 128;
            int mat = c >> 9;
            int row = (c >> 2) & 127;
            int ch  = c & 3;
            const __half* g = (mat ? (Bt + (bn + row) * KDIM) : (A + (bm + row) * KDIM))
                              + k0 + ch * 8;
            uint32_t dst = stage_base + (uint32_t)((mat * TILE_HALFS + row * LDT + ch * 8) * 2);
            cp_async16(dst, g);
        }
    };

    load_stage(0, 0);
    CP_COMMIT();
    load_stage(1, GBK);
    CP_COMMIT();

#pragma unroll 1
    for (int kt = 0; kt < NKT; kt++) {
        CP_WAIT(GSTG - 2);
        __syncthreads();

        int nxt = kt + GSTG - 1;
        if (nxt < NKT) load_stage(nxt % GSTG, nxt * GBK);
        CP_COMMIT();

        const __half* As = sm + (kt % GSTG) * STAGE_HALFS;
        const __half* Bs = As + TILE_HALFS;
#pragma unroll
        for (int kk = 0; kk < GBK; kk += 16) {
            wmma::fragment<wmma::matrix_a, 16, 16, 16, __half, wmma::row_major> af[4];
            wmma::fragment<wmma::matrix_b, 16, 16, 16, __half, wmma::col_major> bf[4];
#pragma unroll
            for (int i = 0; i < 4; i++)
                wmma::load_matrix_sync(af[i], As + (wm * 64 + i * 16) * LDT + kk, LDT);
#pragma unroll
            for (int j = 0; j < 4; j++)
                wmma::load_matrix_sync(bf[j], Bs + (wn * 64 + j * 16) * LDT + kk, LDT);
#pragma unroll
            for (int i = 0; i < 4; i++)
#pragma unroll
                for (int j = 0; j < 4; j++)
                    wmma::mma_sync(acc[i][j], af[i], bf[j], acc[i][j]);
        }
    }

#pragma unroll
    for (int i = 0; i < 4; i++)
#pragma unroll
        for (int j = 0; j < 4; j++)
            wmma::store_matrix_sync(
                C + (bm + wm * 64 + i * 16) * N + bn + wn * 64 + j * 16,
                acc[i][j], N, wmma::mem_row_major);
}

// ---------------- fp32 -> fp16 conversion -----------------------------------
__global__ void to_half(const float4* __restrict__ src, uint2* __restrict__ dst, int n4)
{
    int i = blockIdx.x * blockDim.x + threadIdx.x;
    if (i >= n4) return;
    float4 x = src[i];
    __half2 a = __floats2half2_rn(x.x, x.y);
    __half2 b = __floats2half2_rn(x.z, x.w);
    dst[i] = make_uint2(*(uint32_t*)&a, *(uint32_t*)&b);
}

// src [Kd, Nd] fp32 -> dst [Nd, Kd] fp16 (transpose + convert)
__global__ void transpose_half(const float* __restrict__ src, __half* __restrict__ dst,
                               int Kd, int Nd)
{
    __shared__ float t[32][33];
    int n0 = blockIdx.x * 32, k0 = blockIdx.y * 32;
    int tx = threadIdx.x, ty = threadIdx.y;
#pragma unroll
    for (int r = 0; r < 4; r++)
        t[ty + r * 8][tx] = src[(size_t)(k0 + ty + r * 8) * Nd + n0 + tx];
    __syncthreads();
#pragma unroll
    for (int r = 0; r < 4; r++)
        dst[(size_t)(n0 + ty + r * 8) * Kd + k0 + tx] = __float2half_rn(t[tx][ty + r * 8]);
}

// ---------------- RoPE + split/transpose ------------------------------------
__global__ void rope_split(const float* __restrict__ qkv,
                           float* __restrict__ q, float* __restrict__ k,
                           float* __restrict__ v)
{
    int idx = blockIdx.x * blockDim.x + threadIdx.x;
    const int total = BS * SEQ * NH * HD;
    if (idx >= total) return;
    int d = idx % HD;
    int h = (idx / HD) % NH;
    int s = (idx / (HD * NH)) % SEQ;
    int b = idx / (HD * NH * SEQ);

    const float* base = qkv + (((long)(b * SEQ + s) * 3) * NH + h) * HD;
    float qv = base[d];
    float kv = base[NH * HD + d];
    float vv = base[2 * NH * HD + d];

    int fi = d & 31;
    float inv_freq = expf(-(2.0f * (float)fi / (float)HD) * logf(ROPE_BASE));
    float angle = (float)s * inv_freq;
    float c = cosf(angle), sn = sinf(angle);

    float qo, ko;
    if (d < 32) {
        qo = qv * c - base[d + 32] * sn;
        ko = kv * c - base[NH * HD + d + 32] * sn;
    } else {
        qo = qv * c + base[d - 32] * sn;
        ko = kv * c + base[NH * HD + d - 32] * sn;
    }
    long out = ((long)(b * NH + h) * SEQ + s) * HD + d;
    q[out] = qo;
    k[out] = ko;
    v[out] = vv;
}

// ---------------- sliding-window attention (register-blocked, fp32 math) ----
__global__ __launch_bounds__(256) void attn_kernel(
    const float* __restrict__ q, const float* __restrict__ k,
    const float* __restrict__ v, __half* __restrict__ o)
{
    extern __shared__ float smA[];
    float* Qs = smA;                      // QT*HD
    float* Ks = Qs + QT * HD;             // KT*LDK (reused for V)
    float* Ss = Ks + KT * LDK;            // QT*KT

    const int qt = blockIdx.x;
    const int h  = blockIdx.y;
    const int b  = blockIdx.z;
    const int i0 = qt * QT;
    const int j0 = i0 - WINDOW;
    const int tid = threadIdx.x;

    const float* Qg = q + ((long)(b * NH + h) * SEQ) * HD;
    const float* Kg = k + ((long)(b * NH + h) * SEQ) * HD;
    const float* Vg = v + ((long)(b * NH + h) * SEQ) * HD;

    for (int f = tid; f < QT * HD / 4; f += 256) {
        float4 val = *(const float4*)(Qg + (long)i0 * HD + f * 4);
        *(float4*)(Qs + f * 4) = val;
    }
    for (int f = tid; f < KT * HD / 4; f += 256) {
        int row = f / (HD / 4);
        int c4  = f % (HD / 4);
        int j = j0 + row;
        float4 val = make_float4(0.f, 0.f, 0.f, 0.f);
        if (j >= 0 && j < SEQ) val = *(const float4*)(Kg + (long)j * HD + c4 * 4);
        float* dst = Ks + row * LDK + c4 * 4;
        dst[0] = val.x; dst[1] = val.y; dst[2] = val.z; dst[3] = val.w;
    }
    __syncthreads();

    // ---- S = Q K^T * scale (8q x 6j per thread) ----
    const float scale = 0.125f;
    {
        const int tq0 = (tid >> 5) * 8;
        const int jr0 = (tid & 31) * 6;
        bool block_dead = (jr0 + 5 < tq0) || (jr0 > tq0 + 7 + 2 * WINDOW);

        float acc[8][6];
        if (!block_dead) {
#pragma unroll
            for (int i = 0; i < 8; i++)
#pragma unroll
                for (int j = 0; j < 6; j++) acc[i][j] = 0.0f;
#pragma unroll 4
            for (int d = 0; d < HD; d++) {
                float qv[8], kv[6];
#pragma unroll
                for (int i = 0; i < 8; i++) qv[i] = Qs[(tq0 + i) * HD + d];
#pragma unroll
                for (int j = 0; j < 6; j++) kv[j] = Ks[(jr0 + j) * LDK + d];
#pragma unroll
                for (int i = 0; i < 8; i++)
#pragma unroll
                    for (int j = 0; j < 6; j++)
                        acc[i][j] = fmaf(qv[i], kv[j], acc[i][j]);
            }
        }
#pragma unroll
        for (int i = 0; i < 8; i++) {
            int qr = tq0 + i;
#pragma unroll
            for (int j = 0; j < 6; j++) {
                int jr = jr0 + j;
                int jg = j0 + jr;
                bool valid = !block_dead && (jg >= 0) && (jg < SEQ) &&
                             (jr >= qr) && (jr <= qr + 2 * WINDOW);
                Ss[qr * KT + jr] = valid ? acc[i][j] * scale : -INFINITY;
            }
        }
    }
    __syncthreads();

    // ---- softmax per row ----
    {
        int warp = tid >> 5, lane = tid & 31;
        for (int r = warp * 8; r < warp * 8 + 8; r++) {
            float* row = Ss + r * KT;
            float m = -INFINITY;
            for (int c = lane; c < KT; c += 32) m = fmaxf(m, row[c]);
#pragma unroll
            for (int off = 16; off > 0; off >>= 1)
                m = fmaxf(m, __shfl_xor_sync(0xffffffffu, m, off));
            float sum = 0.0f;
            for (int c = lane; c < KT; c += 32) {
                float e = __expf(row[c] - m);
                if (!isfinite(row[c])) e = 0.0f;
                row[c] = e;
                sum += e;
            }
#pragma unroll
            for (int off = 16; off > 0; off >>= 1)
                sum += __shfl_xor_sync(0xffffffffu, sum, off);
            float inv = 1.0f / sum;
            for (int c = lane; c < KT; c += 32) row[c] *= inv;
        }
    }
    __syncthreads();

    // ---- load V window (reuse Ks) ----
    for (int f = tid; f < KT * HD / 4; f += 256) {
        int row = f / (HD / 4);
        int c4  = f % (HD / 4);
        int j = j0 + row;
        float4 val = make_float4(0.f, 0.f, 0.f, 0.f);
        if (j >= 0 && j < SEQ) val = *(const float4*)(Vg + (long)j * HD + c4 * 4);
        float* dst = Ks + row * LDK + c4 * 4;
        dst[0] = val.x; dst[1] = val.y; dst[2] = val.z; dst[3] = val.w;
    }
    __syncthreads();

    // ---- O = P V (4q x 4d per thread), emit fp16 ----
    {
        const int qr0 = (tid >> 4) * 4;
        const int d0  = (tid & 15) * 4;
        float acc[4][4];
#pragma unroll
        for (int i = 0; i < 4; i++)
#pragma unroll
            for (int j = 0; j < 4; j++) acc[i][j] = 0.0f;

        const int jlo = qr0;
        const int jhi = qr0 + 3 + 2 * WINDOW;
#pragma unroll 2
        for (int j = jlo; j <= (jhi < KT - 1 ? jhi : KT - 1); j++) {
            float vv[4], pv[4];
            const float* vrow = Ks + j * LDK + d0;
#pragma unroll
            for (int t = 0; t < 4; t++) vv[t] = vrow[t];
#pragma unroll
            for (int i = 0; i < 4; i++) pv[i] = Ss[(qr0 + i) * KT + j];
#pragma unroll
            for (int i = 0; i < 4; i++)
#pragma unroll
                for (int t = 0; t < 4; t++)
                    acc[i][t] = fmaf(pv[i], vv[t], acc[i][t]);
        }
#pragma unroll
        for (int i = 0; i < 4; i++) {
            long orow = ((long)(b * SEQ + i0 + qr0 + i)) * DIM + h * HD + d0;
            __half2 h01 = __floats2half2_rn(acc[i][0], acc[i][1]);
            __half2 h23 = __floats2half2_rn(acc[i][2], acc[i][3]);
            *(uint2*)(o + orow) = make_uint2(*(uint32_t*)&h01, *(uint32_t*)&h23);
        }
    }
}

// ---------------------------------------------------------------------------
extern "C" void kernel_launch(void* const* d_in, const int* in_sizes, int n_in,
                              void* d_out, int out_size)
{
    const float* hs   = (const float*)d_in[0];
    const float* Wqkv = (const float*)d_in[1];
    const float* Wo   = (const float*)d_in[2];
    float* out = (float*)d_out;

    float *qkv, *q, *k, *v;
    __half *hs_h, *w1t, *wot, *att;
    cudaGetSymbolAddress((void**)&qkv,  g_qkv);
    cudaGetSymbolAddress((void**)&q,    g_q);
    cudaGetSymbolAddress((void**)&k,    g_k);
    cudaGetSymbolAddress((void**)&v,    g_v);
    cudaGetSymbolAddress((void**)&hs_h, g_hs_h);
    cudaGetSymbolAddress((void**)&w1t,  g_w1t);
    cudaGetSymbolAddress((void**)&wot,  g_wot);
    cudaGetSymbolAddress((void**)&att,  g_att);

    cudaFuncSetAttribute(gemm_f16, cudaFuncAttributeMaxDynamicSharedMemorySize, GEMM_SMEM);
    int smem_attn = (QT * HD + KT * LDK + QT * KT) * (int)sizeof(float);
    cudaFuncSetAttribute(attn_kernel, cudaFuncAttributeMaxDynamicSharedMemorySize, smem_attn);

    // 0) convert inputs to fp16 (weights also transposed to [N,K])
    {
        int n4 = MROWS * DIM / 4;
        to_half<<<(n4 + 255) / 256, 256>>>((const float4*)hs, (uint2*)hs_h, n4);
        transpose_half<<<dim3(3 * DIM / 32, DIM / 32), dim3(32, 8)>>>(Wqkv, w1t, DIM, 3 * DIM);
        transpose_half<<<dim3(DIM / 32, DIM / 32), dim3(32, 8)>>>(Wo, wot, DIM, DIM);
    }

    // 1) QKV projection: [4096,768] @ [768,2304] (fp16 HMMA, fp32 acc)
    gemm_f16<<<dim3(3 * DIM / GBN, MROWS / GBM), 128, GEMM_SMEM>>>(hs_h, w1t, qkv, 3 * DIM);

    // 2) RoPE + split
    {
        int total = BS * SEQ * NH * HD;
        rope_split<<<(total + 255) / 256, 256>>>(qkv, q, k, v);
    }

    // 3) sliding-window attention (fp32 math, fp16 output)
    {
        dim3 grid(SEQ / QT, NH, BS);
        attn_kernel<<<grid, 256, smem_attn>>>(q, k, v, att);
    }

    // 4) output projection: [4096,768] @ [768,768]
    gemm_f16<<<dim3(DIM / GBN, MROWS / GBM), 128, GEMM_SMEM>>>(att, wot, out, DIM);
}

// round 7
// speedup vs baseline: 6.0505x; 1.5821x over previous
#include <cuda_runtime.h>
#include <cuda_fp16.h>
#include <mma.h>
#include <math.h>
#include <stdint.h>

using namespace nvcuda;

#define BS 2
#define SEQ 2048
#define DIM 768
#define NH 12
#define HD 64
#define WINDOW 64
#define ROPE_BASE 10000.0f

#define QT 64          // query tile
#define KTW 192        // key window per tile
#define LDQ 72         // Q smem stride (halfs)
#define LDKV 72        // K/V smem stride (halfs)
#define LDS 200        // S smem stride (floats)
#define LDP 200        // P smem stride (halfs)
#define LDO 72         // O staging stride (floats)
#define ATTN_SMEM (QT*LDQ*2 + KTW*LDKV*2 + QT*LDS*4 + QT*LDP*2)  // 113664 B

#define MROWS 4096     // BS*SEQ
#define KDIM 768

// ---- GEMM tiling: CTA 128x128, 4 warps (2x2) of 64x64, BK=32 fp16, 3 stages
#define GBM 128
#define GBN 128
#define GBK 32
#define GSTG 3
#define LDT 40
#define TILE_HALFS (GBM * LDT)
#define STAGE_HALFS (2 * TILE_HALFS)
#define GEMM_SMEM (GSTG * STAGE_HALFS * 2)
#define NKT (KDIM / GBK)

// ---------------- scratch (static device memory; no allocs) ----------------
__device__ float  g_qkv[MROWS * 3 * DIM];
__device__ __half g_q[BS * NH * SEQ * HD];
__device__ __half g_k[BS * NH * SEQ * HD];
__device__ __half g_v[BS * NH * SEQ * HD];
__device__ __half g_hs_h[MROWS * DIM];
__device__ __half g_w1t[3 * DIM * DIM];
__device__ __half g_wot[DIM * DIM];
__device__ __half g_att[MROWS * DIM];

// ---------------- cp.async helpers -----------------------------------------
__device__ __forceinline__ uint32_t smem_u32(const void* p) {
    uint32_t a;
    asm("{ .reg .u64 t; cvta.to.shared.u64 t, %1; cvt.u32.u64 %0, t; }" : "=r"(a) : "l"(p));
    return a;
}
__device__ __forceinline__ void cp_async16(uint32_t dst, const void* src) {
    asm volatile("cp.async.cg.shared.global [%0], [%1], 16;" :: "r"(dst), "l"(src));
}
#define CP_COMMIT() asm volatile("cp.async.commit_group;" ::: "memory")
#define CP_WAIT(n)  asm volatile("cp.async.wait_group %0;" :: "n"(n) : "memory")

// ---------------- fp16 mma GEMM: C[M,N] = A[M,768] @ Bt[N,768]^T ------------
__global__ __launch_bounds__(128) void gemm_f16(
    const __half* __restrict__ A, const __half* __restrict__ Bt,
    float* __restrict__ C, int N)
{
    extern __shared__ __half sm[];
    const uint32_t sbase = smem_u32(sm);
    const int tid = threadIdx.x;
    const int warp = tid >> 5;
    const int wm = warp >> 1;
    const int wn = warp & 1;
    const long bm = (long)blockIdx.y * GBM;
    const long bn = (long)blockIdx.x * GBN;

    wmma::fragment<wmma::accumulator, 16, 16, 16, float> acc[4][4];
#pragma unroll
    for (int i = 0; i < 4; i++)
#pragma unroll
        for (int j = 0; j < 4; j++) wmma::fill_fragment(acc[i][j], 0.0f);

    auto load_stage = [&](int buf, int k0) {
        uint32_t stage_base = sbase + (uint32_t)(buf * STAGE_HALFS * 2);
#pragma unroll
        for (int it = 0; it < 8; it++) {
            int c = tid + it * 128;
            int mat = c >> 9;
            int row = (c >> 2) & 127;
            int ch  = c & 3;
            const __half* g = (mat ? (Bt + (bn + row) * KDIM) : (A + (bm + row) * KDIM))
                              + k0 + ch * 8;
            uint32_t dst = stage_base + (uint32_t)((mat * TILE_HALFS + row * LDT + ch * 8) * 2);
            cp_async16(dst, g);
        }
    };

    load_stage(0, 0);
    CP_COMMIT();
    load_stage(1, GBK);
    CP_COMMIT();

#pragma unroll 1
    for (int kt = 0; kt < NKT; kt++) {
        CP_WAIT(GSTG - 2);
        __syncthreads();

        int nxt = kt + GSTG - 1;
        if (nxt < NKT) load_stage(nxt % GSTG, nxt * GBK);
        CP_COMMIT();

        const __half* As = sm + (kt % GSTG) * STAGE_HALFS;
        const __half* Bs = As + TILE_HALFS;
#pragma unroll
        for (int kk = 0; kk < GBK; kk += 16) {
            wmma::fragment<wmma::matrix_a, 16, 16, 16, __half, wmma::row_major> af[4];
            wmma::fragment<wmma::matrix_b, 16, 16, 16, __half, wmma::col_major> bf[4];
#pragma unroll
            for (int i = 0; i < 4; i++)
                wmma::load_matrix_sync(af[i], As + (wm * 64 + i * 16) * LDT + kk, LDT);
#pragma unroll
            for (int j = 0; j < 4; j++)
                wmma::load_matrix_sync(bf[j], Bs + (wn * 64 + j * 16) * LDT + kk, LDT);
#pragma unroll
            for (int i = 0; i < 4; i++)
#pragma unroll
                for (int j = 0; j < 4; j++)
                    wmma::mma_sync(acc[i][j], af[i], bf[j], acc[i][j]);
        }
    }

#pragma unroll
    for (int i = 0; i < 4; i++)
#pragma unroll
        for (int j = 0; j < 4; j++)
            wmma::store_matrix_sync(
                C + (bm + wm * 64 + i * 16) * N + bn + wn * 64 + j * 16,
                acc[i][j], N, wmma::mem_row_major);
}

// ---------------- fp32 -> fp16 conversion -----------------------------------
__global__ void to_half(const float4* __restrict__ src, uint2* __restrict__ dst, int n4)
{
    int i = blockIdx.x * blockDim.x + threadIdx.x;
    if (i >= n4) return;
    float4 x = src[i];
    __half2 a = __floats2half2_rn(x.x, x.y);
    __half2 b = __floats2half2_rn(x.z, x.w);
    dst[i] = make_uint2(*(uint32_t*)&a, *(uint32_t*)&b);
}

__global__ void transpose_half(const float* __restrict__ src, __half* __restrict__ dst,
                               int Kd, int Nd)
{
    __shared__ float t[32][33];
    int n0 = blockIdx.x * 32, k0 = blockIdx.y * 32;
    int tx = threadIdx.x, ty = threadIdx.y;
#pragma unroll
    for (int r = 0; r < 4; r++)
        t[ty + r * 8][tx] = src[(size_t)(k0 + ty + r * 8) * Nd + n0 + tx];
    __syncthreads();
#pragma unroll
    for (int r = 0; r < 4; r++)
        dst[(size_t)(n0 + ty + r * 8) * Kd + k0 + tx] = __float2half_rn(t[tx][ty + r * 8]);
}

// ---------------- RoPE + split/transpose -> fp16 q/k/v ----------------------
__global__ void rope_split(const float* __restrict__ qkv,
                           __half* __restrict__ q, __half* __restrict__ k,
                           __half* __restrict__ v)
{
    int idx = blockIdx.x * blockDim.x + threadIdx.x;
    const int total = BS * SEQ * NH * HD;
    if (idx >= total) return;
    int d = idx % HD;
    int h = (idx / HD) % NH;
    int s = (idx / (HD * NH)) % SEQ;
    int b = idx / (HD * NH * SEQ);

    const float* base = qkv + (((long)(b * SEQ + s) * 3) * NH + h) * HD;
    float qv = base[d];
    float kv = base[NH * HD + d];
    float vv = base[2 * NH * HD + d];

    int fi = d & 31;
    float inv_freq = expf(-(2.0f * (float)fi / (float)HD) * logf(ROPE_BASE));
    float angle = (float)s * inv_freq;
    float c = cosf(angle), sn = sinf(angle);

    float qo, ko;
    if (d < 32) {
        qo = qv * c - base[d + 32] * sn;
        ko = kv * c - base[NH * HD + d + 32] * sn;
    } else {
        qo = qv * c + base[d - 32] * sn;
        ko = kv * c + base[NH * HD + d - 32] * sn;
    }
    long out = ((long)(b * NH + h) * SEQ + s) * HD + d;
    q[out] = __float2half_rn(qo);
    k[out] = __float2half_rn(ko);
    v[out] = __float2half_rn(vv);
}

// ---------------- sliding-window attention (fp16 WMMA, fp32 softmax) --------
__global__ __launch_bounds__(256) void attn_kernel(
    const __half* __restrict__ q, const __half* __restrict__ k,
    const __half* __restrict__ v, __half* __restrict__ o)
{
    extern __shared__ char smraw[];
    __half* Qs  = (__half*)smraw;                        // QT*LDQ halfs
    __half* KVs = Qs + QT * LDQ;                         // KTW*LDKV halfs
    float*  Ss  = (float*)(KVs + KTW * LDKV);            // QT*LDS floats (reused as O staging)
    __half* Ps  = (__half*)(Ss + QT * LDS);              // QT*LDP halfs

    const int qt = blockIdx.x;
    const int h  = blockIdx.y;
    const int b  = blockIdx.z;
    const int i0 = qt * QT;
    const int j0 = i0 - WINDOW;
    const int tid = threadIdx.x;
    const int warp = tid >> 5;
    const int lane = tid & 31;

    const __half* Qg = q + ((long)(b * NH + h) * SEQ) * HD;
    const __half* Kg = k + ((long)(b * NH + h) * SEQ) * HD;
    const __half* Vg = v + ((long)(b * NH + h) * SEQ) * HD;

    // ---- load Q (64x64) and K window (192x64, zero-padded) ----
    for (int f = tid; f < QT * 8; f += 256) {
        int row = f >> 3, c8 = f & 7;
        uint4 val = *(const uint4*)(Qg + (long)(i0 + row) * HD + c8 * 8);
        *(uint4*)(Qs + row * LDQ + c8 * 8) = val;
    }
    for (int f = tid; f < KTW * 8; f += 256) {
        int row = f >> 3, c8 = f & 7;
        int j = j0 + row;
        uint4 val = make_uint4(0u, 0u, 0u, 0u);
        if (j >= 0 && j < SEQ) val = *(const uint4*)(Kg + (long)j * HD + c8 * 8);
        *(uint4*)(KVs + row * LDKV + c8 * 8) = val;
    }
    __syncthreads();

    // ---- S = Q @ K^T : 8 warps, warp -> 16-row strip x 96-col half ----
    {
        const int wr = (warp & 3) * 16;
        const int wc = (warp >> 2) * 96;
        wmma::fragment<wmma::matrix_a, 16, 16, 16, __half, wmma::row_major> af[4];
#pragma unroll
        for (int kk = 0; kk < 4; kk++)
            wmma::load_matrix_sync(af[kk], Qs + wr * LDQ + kk * 16, LDQ);
#pragma unroll
        for (int jt = 0; jt < 6; jt++) {
            wmma::fragment<wmma::accumulator, 16, 16, 16, float> acc;
            wmma::fill_fragment(acc, 0.0f);
#pragma unroll
            for (int kk = 0; kk < 4; kk++) {
                wmma::fragment<wmma::matrix_b, 16, 16, 16, __half, wmma::col_major> bf;
                wmma::load_matrix_sync(bf, KVs + (wc + jt * 16) * LDKV + kk * 16, LDKV);
                wmma::mma_sync(acc, af[kk], bf, acc);
            }
            wmma::store_matrix_sync(Ss + wr * LDS + wc + jt * 16, acc, LDS, wmma::mem_row_major);
        }
    }
    __syncthreads();

    // ---- load V window into KVs (K no longer needed) ----
    for (int f = tid; f < KTW * 8; f += 256) {
        int row = f >> 3, c8 = f & 7;
        int j = j0 + row;
        uint4 val = make_uint4(0u, 0u, 0u, 0u);
        if (j >= 0 && j < SEQ) val = *(const uint4*)(Vg + (long)j * HD + c8 * 8);
        *(uint4*)(KVs + row * LDKV + c8 * 8) = val;
    }

    // ---- softmax: warp -> 8 rows, lane -> 6 strided cols; P -> fp16 ----
    {
        const float scale = 0.125f;
#pragma unroll
        for (int rr = 0; rr < 8; rr++) {
            int r = warp * 8 + rr;
            float e[6];
            float m = -INFINITY;
#pragma unroll
            for (int t = 0; t < 6; t++) {
                int c = lane + 32 * t;
                int jg = j0 + c;
                bool valid = (c >= r) && (c <= r + 2 * WINDOW) && (jg >= 0) && (jg < SEQ);
                float s = valid ? Ss[r * LDS + c] * scale : -INFINITY;
                e[t] = s;
                m = fmaxf(m, s);
            }
#pragma unroll
            for (int off = 16; off > 0; off >>= 1)
                m = fmaxf(m, __shfl_xor_sync(0xffffffffu, m, off));
            float sum = 0.0f;
#pragma unroll
            for (int t = 0; t < 6; t++) {
                e[t] = __expf(e[t] - m);       // exp(-inf) = 0 for masked
                sum += e[t];
            }
#pragma unroll
            for (int off = 16; off > 0; off >>= 1)
                sum += __shfl_xor_sync(0xffffffffu, sum, off);
            float inv = 1.0f / sum;
#pragma unroll
            for (int t = 0; t < 6; t++)
                Ps[r * LDP + lane + 32 * t] = __float2half_rn(e[t] * inv);
        }
    }
    __syncthreads();

    // ---- O = P @ V : warp -> 16-row strip x 32-col half; stage fp32 in Ss ----
    {
        const int wr = (warp & 3) * 16;
        const int wc = (warp >> 2) * 32;
        wmma::fragment<wmma::accumulator, 16, 16, 16, float> acc[2];
        wmma::fill_fragment(acc[0], 0.0f);
        wmma::fill_fragment(acc[1], 0.0f);
#pragma unroll
        for (int kk = 0; kk < 12; kk++) {
            wmma::fragment<wmma::matrix_a, 16, 16, 16, __half, wmma::row_major> af;
            wmma::load_matrix_sync(af, Ps + wr * LDP + kk * 16, LDP);
#pragma unroll
            for (int t = 0; t < 2; t++) {
                wmma::fragment<wmma::matrix_b, 16, 16, 16, __half, wmma::row_major> bf;
                wmma::load_matrix_sync(bf, KVs + kk * 16 * LDKV + wc + t * 16, LDKV);
                wmma::mma_sync(acc[t], af, bf, acc[t]);
            }
        }
#pragma unroll
        for (int t = 0; t < 2; t++)
            wmma::store_matrix_sync(Ss + wr * LDO + wc + t * 16, acc[t], LDO, wmma::mem_row_major);
    }
    __syncthreads();

    // ---- write O (64x64 fp32 staging -> fp16 global) ----
    for (int idx = tid; idx < QT * 16; idx += 256) {
        int row = idx >> 4;
        int c4  = (idx & 15) * 4;
        const float* src = Ss + row * LDO + c4;
        __half2 h01 = __floats2half2_rn(src[0], src[1]);
        __half2 h23 = __floats2half2_rn(src[2], src[3]);
        long orow = ((long)(b * SEQ + i0 + row)) * DIM + h * HD + c4;
        *(uint2*)(o + orow) = make_uint2(*(uint32_t*)&h01, *(uint32_t*)&h23);
    }
}

// ---------------------------------------------------------------------------
extern "C" void kernel_launch(void* const* d_in, const int* in_sizes, int n_in,
                              void* d_out, int out_size)
{
    const float* hs   = (const float*)d_in[0];
    const float* Wqkv = (const float*)d_in[1];
    const float* Wo   = (const float*)d_in[2];
    float* out = (float*)d_out;

    float* qkv;
    __half *q, *k, *v, *hs_h, *w1t, *wot, *att;
    cudaGetSymbolAddress((void**)&qkv,  g_qkv);
    cudaGetSymbolAddress((void**)&q,    g_q);
    cudaGetSymbolAddress((void**)&k,    g_k);
    cudaGetSymbolAddress((void**)&v,    g_v);
    cudaGetSymbolAddress((void**)&hs_h, g_hs_h);
    cudaGetSymbolAddress((void**)&w1t,  g_w1t);
    cudaGetSymbolAddress((void**)&wot,  g_wot);
    cudaGetSymbolAddress((void**)&att,  g_att);

    cudaFuncSetAttribute(gemm_f16, cudaFuncAttributeMaxDynamicSharedMemorySize, GEMM_SMEM);
    cudaFuncSetAttribute(attn_kernel, cudaFuncAttributeMaxDynamicSharedMemorySize, ATTN_SMEM);

    // 0) convert inputs to fp16
    {
        int n4 = MROWS * DIM / 4;
        to_half<<<(n4 + 255) / 256, 256>>>((const float4*)hs, (uint2*)hs_h, n4);
        transpose_half<<<dim3(3 * DIM / 32, DIM / 32), dim3(32, 8)>>>(Wqkv, w1t, DIM, 3 * DIM);
        transpose_half<<<dim3(DIM / 32, DIM / 32), dim3(32, 8)>>>(Wo, wot, DIM, DIM);
    }

    // 1) QKV projection (fp16 HMMA, fp32 acc)
    gemm_f16<<<dim3(3 * DIM / GBN, MROWS / GBM), 128, GEMM_SMEM>>>(hs_h, w1t, qkv, 3 * DIM);

    // 2) RoPE + split -> fp16 q/k/v
    {
        int total = BS * SEQ * NH * HD;
        rope_split<<<(total + 255) / 256, 256>>>(qkv, q, k, v);
    }

    // 3) sliding-window attention (fp16 tensor cores)
    {
        dim3 grid(SEQ / QT, NH, BS);
        attn_kernel<<<grid, 256, ATTN_SMEM>>>(q, k, v, att);
    }

    // 4) output projection
    gemm_f16<<<dim3(DIM / GBN, MROWS / GBM), 128, GEMM_SMEM>>>(att, wot, out, DIM);
}